// round 11
// baseline (speedup 1.0000x reference)
#include <cuda_runtime.h>
#include <math.h>

#define NUM_LEVELS 16
#define TABLE_SIZE (1u << 19)
#define HASH_MASK  (TABLE_SIZE - 1u)
#define P2 2654435761u
#define P3 805459861u

#define CAP   2097152      // max points supported by sort path (N = 2,000,000)
#define NBINS (1u << 18)   // 64^3 Morton bins
#define SCAN_BLOCKS 256    // 256 blocks x 1024 threads covers NBINS

struct LevelCfg {
    float scale[NUM_LEVELS];
    unsigned int res[NUM_LEVELS];
};

// ---- scratch (static __device__ globals; no allocation) ----
__device__ float4       g_pts[CAP];        // sorted: (tx,ty,tz, bit-cast original idx)
__device__ unsigned int g_hist[NBINS];
__device__ unsigned int g_scan[NBINS];
__device__ unsigned int g_cursor[NBINS];
__device__ unsigned int g_bsum[SCAN_BLOCKS];
__device__ unsigned int g_bsumscan[SCAN_BLOCKS];

// ---- MLP weights in constant memory (uniform-const port, off the L1TEX pipe) ----
__constant__ float cW1[1024];
__constant__ float cW2[1024];
__constant__ float cW3[128];

// ---- helpers ----
__device__ __forceinline__ unsigned int expand_bits(unsigned int v) {
    v = (v * 0x00010001u) & 0xFF0000FFu;
    v = (v * 0x00000101u) & 0x0F00F00Fu;
    v = (v * 0x00000011u) & 0xC30C30C3u;
    v = (v * 0x00000005u) & 0x49249249u;
    return v;
}

__device__ __forceinline__ void norm_coords(const float* __restrict__ points,
                                            const float* __restrict__ aabb,
                                            int n, float& tx, float& ty, float& tz)
{
    float a0 = __ldg(aabb + 0), a1 = __ldg(aabb + 1), a2 = __ldg(aabb + 2);
    float b0 = __ldg(aabb + 3), b1 = __ldg(aabb + 4), b2 = __ldg(aabb + 5);
    tx = fminf(fmaxf((points[3 * n + 0] - a0) / (b0 - a0), 0.0f), 1.0f);
    ty = fminf(fmaxf((points[3 * n + 1] - a1) / (b1 - a1), 0.0f), 1.0f);
    tz = fminf(fmaxf((points[3 * n + 2] - a2) / (b2 - a2), 0.0f), 1.0f);
}

__device__ __forceinline__ unsigned int morton_bin(float tx, float ty, float tz) {
    unsigned int bx = min((unsigned int)(tx * 64.0f), 63u);
    unsigned int by = min((unsigned int)(ty * 64.0f), 63u);
    unsigned int bz = min((unsigned int)(tz * 64.0f), 63u);
    return expand_bits(bx) | (expand_bits(by) << 1) | (expand_bits(bz) << 2);
}

// ---- sort pipeline kernels ----
__global__ void zero_hist_kernel() {
    unsigned int i = blockIdx.x * blockDim.x + threadIdx.x;
    uint4 z = make_uint4(0u, 0u, 0u, 0u);
    if (i < NBINS / 4) reinterpret_cast<uint4*>(g_hist)[i] = z;
}

__global__ void hist_kernel(const float* __restrict__ points,
                            const float* __restrict__ aabb, int N) {
    int n = blockIdx.x * blockDim.x + threadIdx.x;
    if (n >= N) return;
    float tx, ty, tz;
    norm_coords(points, aabb, n, tx, ty, tz);
    atomicAdd(&g_hist[morton_bin(tx, ty, tz)], 1u);
}

// per-block (1024-bin) inclusive scan, warp-shuffle based
__global__ void scan1_kernel() {
    __shared__ unsigned int warp_sums[32];
    unsigned int i = blockIdx.x * 1024 + threadIdx.x;
    unsigned int lane = threadIdx.x & 31u;
    unsigned int warp = threadIdx.x >> 5;

    unsigned int v = g_hist[i];
    unsigned int x = v;
#pragma unroll
    for (int off = 1; off < 32; off <<= 1) {
        unsigned int t = __shfl_up_sync(0xFFFFFFFFu, x, off);
        if (lane >= (unsigned)off) x += t;
    }
    if (lane == 31u) warp_sums[warp] = x;
    __syncthreads();
    if (warp == 0u) {
        unsigned int s = warp_sums[lane];
#pragma unroll
        for (int off = 1; off < 32; off <<= 1) {
            unsigned int t = __shfl_up_sync(0xFFFFFFFFu, s, off);
            if (lane >= (unsigned)off) s += t;
        }
        warp_sums[lane] = s;
    }
    __syncthreads();
    unsigned int incl = x + (warp > 0u ? warp_sums[warp - 1u] : 0u);
    g_scan[i] = incl;
    if (threadIdx.x == 1023u) g_bsum[blockIdx.x] = incl;
}

__global__ void scan2_kernel() {  // exclusive scan of block sums (1 block, 256 thr)
    __shared__ unsigned int warp_sums[8];
    unsigned int t = threadIdx.x;
    unsigned int lane = t & 31u, warp = t >> 5;
    unsigned int v = g_bsum[t];
    unsigned int x = v;
#pragma unroll
    for (int off = 1; off < 32; off <<= 1) {
        unsigned int y = __shfl_up_sync(0xFFFFFFFFu, x, off);
        if (lane >= (unsigned)off) x += y;
    }
    if (lane == 31u) warp_sums[warp] = x;
    __syncthreads();
    if (warp == 0u && lane < 8u) {
        unsigned int s = warp_sums[lane];
#pragma unroll
        for (int off = 1; off < 8; off <<= 1) {
            unsigned int y = __shfl_up_sync(0xFFu, s, off);
            if (lane >= (unsigned)off) s += y;
        }
        warp_sums[lane] = s;
    }
    __syncthreads();
    unsigned int incl = x + (warp > 0u ? warp_sums[warp - 1u] : 0u);
    g_bsumscan[t] = incl - v;  // exclusive
}

__global__ void scan3_kernel() {  // global exclusive offsets -> cursors
    unsigned int i = blockIdx.x * 1024 + threadIdx.x;
    g_cursor[i] = g_scan[i] - g_hist[i] + g_bsumscan[blockIdx.x];
}

__global__ void scatter_kernel(const float* __restrict__ points,
                               const float* __restrict__ aabb, int N) {
    int n = blockIdx.x * blockDim.x + threadIdx.x;
    if (n >= N) return;
    float tx, ty, tz;
    norm_coords(points, aabb, n, tx, ty, tz);
    unsigned int p = atomicAdd(&g_cursor[morton_bin(tx, ty, tz)], 1u);
    g_pts[p] = make_float4(tx, ty, tz, __uint_as_float((unsigned int)n));
}

__global__ void stage_identity_kernel(const float* __restrict__ points,
                                      const float* __restrict__ aabb, int N) {
    int n = blockIdx.x * blockDim.x + threadIdx.x;
    if (n >= N) return;
    float tx, ty, tz;
    norm_coords(points, aabb, n, tx, ty, tz);
    g_pts[n] = make_float4(tx, ty, tz, __uint_as_float((unsigned int)n));
}

// Load a corner x-pair (iA, iB): adjacent+aligned -> one LDG.128.
__device__ __forceinline__ void load_pair(const float2* __restrict__ tab,
                                          unsigned int iA, unsigned int iB,
                                          float2& vA, float2& vB)
{
    if (((iA & 1u) == 0u) && (iB == iA + 1u)) {
        float4 t = __ldg(reinterpret_cast<const float4*>(tab + iA));
        vA.x = t.x; vA.y = t.y;
        vB.x = t.z; vB.y = t.w;
    } else {
        vA = __ldg(tab + iA);
        vB = __ldg(tab + iB);
    }
}

__global__ void __launch_bounds__(128, 6)
hashmlp_kernel(const float* __restrict__ tables,
               float* __restrict__ out,
               int N, LevelCfg cfg)
{
    int n = blockIdx.x * blockDim.x + threadIdx.x;
    if (n >= N) return;

    float4 p = g_pts[n];
    float tx = p.x, ty = p.y, tz = p.z;
    unsigned int n_out = __float_as_uint(p.w);

    float h1[32];
#pragma unroll
    for (int i = 0; i < 32; i++) h1[i] = 0.0f;

#pragma unroll
    for (int l = 0; l < NUM_LEVELS; l++) {
        float sc = cfg.scale[l];
        unsigned int res = cfg.res[l];

        float fpx = tx * sc + 0.5f;
        float fpy = ty * sc + 0.5f;
        float fpz = tz * sc + 0.5f;
        float flx = floorf(fpx), fly = floorf(fpy), flz = floorf(fpz);
        float wx = fpx - flx, wy = fpy - fly, wz = fpz - flz;
        unsigned int bx = (unsigned int)flx;
        unsigned int by = (unsigned int)fly;
        unsigned int bz = (unsigned int)flz;
        unsigned int rm1 = res - 1u;
        unsigned int x0 = min(bx, rm1),      x1 = min(bx + 1u, rm1);
        unsigned int y0 = min(by, rm1),      y1 = min(by + 1u, rm1);
        unsigned int z0 = min(bz, rm1),      z1 = min(bz + 1u, rm1);

        unsigned int i0, i1, i2, i3, i4, i5, i6, i7;
        if (l <= 4) {
            unsigned int rr = res * res;
            unsigned int Y0 = y0 * res, Y1 = y1 * res;
            unsigned int Z0 = z0 * rr,  Z1 = z1 * rr;
            i0 = x0 + Y0 + Z0; i1 = x1 + Y0 + Z0;
            i2 = x0 + Y1 + Z0; i3 = x1 + Y1 + Z0;
            i4 = x0 + Y0 + Z1; i5 = x1 + Y0 + Z1;
            i6 = x0 + Y1 + Z1; i7 = x1 + Y1 + Z1;
        } else {
            unsigned int Y0 = y0 * P2, Y1 = y1 * P2;
            unsigned int Z0 = z0 * P3, Z1 = z1 * P3;
            i0 = (x0 ^ Y0 ^ Z0) & HASH_MASK; i1 = (x1 ^ Y0 ^ Z0) & HASH_MASK;
            i2 = (x0 ^ Y1 ^ Z0) & HASH_MASK; i3 = (x1 ^ Y1 ^ Z0) & HASH_MASK;
            i4 = (x0 ^ Y0 ^ Z1) & HASH_MASK; i5 = (x1 ^ Y0 ^ Z1) & HASH_MASK;
            i6 = (x0 ^ Y1 ^ Z1) & HASH_MASK; i7 = (x1 ^ Y1 ^ Z1) & HASH_MASK;
        }

        const float2* tab = reinterpret_cast<const float2*>(tables) + (size_t)l * TABLE_SIZE;
        float2 v0, v1, v2, v3, v4, v5, v6, v7;
        load_pair(tab, i0, i1, v0, v1);
        load_pair(tab, i2, i3, v2, v3);
        load_pair(tab, i4, i5, v4, v5);
        load_pair(tab, i6, i7, v6, v7);

        float ox = 1.0f - wx, oy = 1.0f - wy, oz = 1.0f - wz;
        float w0 = ox * oy * oz, w1c = wx * oy * oz;
        float w2c = ox * wy * oz, w3c = wx * wy * oz;
        float w4c = ox * oy * wz, w5c = wx * oy * wz;
        float w6c = ox * wy * wz, w7c = wx * wy * wz;

        float f0 = w0 * v0.x;
        float f1 = w0 * v0.y;
        f0 = fmaf(w1c, v1.x, f0); f1 = fmaf(w1c, v1.y, f1);
        f0 = fmaf(w2c, v2.x, f0); f1 = fmaf(w2c, v2.y, f1);
        f0 = fmaf(w3c, v3.x, f0); f1 = fmaf(w3c, v3.y, f1);
        f0 = fmaf(w4c, v4.x, f0); f1 = fmaf(w4c, v4.y, f1);
        f0 = fmaf(w5c, v5.x, f0); f1 = fmaf(w5c, v5.y, f1);
        f0 = fmaf(w6c, v6.x, f0); f1 = fmaf(w6c, v6.y, f1);
        f0 = fmaf(w7c, v7.x, f0); f1 = fmaf(w7c, v7.y, f1);

        // Fused layer-1 accumulation; cW1 offsets are compile-time constants.
#pragma unroll
        for (int i = 0; i < 32; i++) {
            h1[i] = fmaf(cW1[i * 32 + 2 * l], f0,
                    fmaf(cW1[i * 32 + 2 * l + 1], f1, h1[i]));
        }
    }

#pragma unroll
    for (int i = 0; i < 32; i++) h1[i] = fmaxf(h1[i], 0.0f);

    // Layers 2+3 fused streaming: h2_i computed then immediately consumed.
    // Removes the h2[32] register array (lower pressure -> higher occupancy).
    float o0 = 0.0f, o1 = 0.0f, o2 = 0.0f, o3 = 0.0f;
#pragma unroll
    for (int i = 0; i < 32; i++) {
        float acc = 0.0f;
#pragma unroll
        for (int j = 0; j < 32; j++) acc = fmaf(cW2[i * 32 + j], h1[j], acc);
        acc = fmaxf(acc, 0.0f);
        o0 = fmaf(cW3[0 * 32 + i], acc, o0);
        o1 = fmaf(cW3[1 * 32 + i], acc, o1);
        o2 = fmaf(cW3[2 * 32 + i], acc, o2);
        o3 = fmaf(cW3[3 * 32 + i], acc, o3);
    }

    float4 r;
    r.x = 1.0f / (1.0f + __expf(-o0));
    r.y = 1.0f / (1.0f + __expf(-o1));
    r.z = 1.0f / (1.0f + __expf(-o2));
    r.w = 1.0f / (1.0f + __expf(-o3)) * 0.99f + 0.01f;

    reinterpret_cast<float4*>(out)[n_out] = r;
}

extern "C" void kernel_launch(void* const* d_in, const int* in_sizes, int n_in,
                              void* d_out, int out_size)
{
    const float* points = (const float*)d_in[0];
    const float* tables = (const float*)d_in[1];
    const float* W1     = (const float*)d_in[2];
    const float* W2     = (const float*)d_in[3];
    const float* W3     = (const float*)d_in[4];
    const float* aabb   = (const float*)d_in[5];
    float* out = (float*)d_out;

    int N = in_sizes[0] / 3;

    LevelCfg cfg;
    double s = exp(log(4096.0 / 16.0) / (double)(NUM_LEVELS - 1));
    for (int l = 0; l < NUM_LEVELS; l++) {
        double sc = 16.0 * pow(s, (double)l) - 1.0;
        cfg.scale[l] = (float)sc;
        cfg.res[l]   = (unsigned int)ceil(sc) + 1u;
    }

    // Weights -> constant memory (D2D async copies; graph-capturable, no allocs)
    cudaMemcpyToSymbolAsync(cW1, W1, 1024 * sizeof(float), 0, cudaMemcpyDeviceToDevice);
    cudaMemcpyToSymbolAsync(cW2, W2, 1024 * sizeof(float), 0, cudaMemcpyDeviceToDevice);
    cudaMemcpyToSymbolAsync(cW3, W3, 128 * sizeof(float), 0, cudaMemcpyDeviceToDevice);

    int block = 256;
    int pgrid = (N + block - 1) / block;

    if (N <= CAP) {
        zero_hist_kernel<<<(NBINS / 4 + 255) / 256, 256>>>();
        hist_kernel<<<pgrid, block>>>(points, aabb, N);
        scan1_kernel<<<SCAN_BLOCKS, 1024>>>();
        scan2_kernel<<<1, SCAN_BLOCKS>>>();
        scan3_kernel<<<SCAN_BLOCKS, 1024>>>();
        scatter_kernel<<<pgrid, block>>>(points, aabb, N);
    } else {
        stage_identity_kernel<<<pgrid, block>>>(points, aabb, N);
    }

    int mblock = 128;
    int mgrid = (N + mblock - 1) / mblock;
    hashmlp_kernel<<<mgrid, mblock>>>(tables, out, N, cfg);
}

// round 12
// speedup vs baseline: 1.1575x; 1.1575x over previous
#include <cuda_runtime.h>
#include <math.h>

#define NUM_LEVELS 16
#define TABLE_SIZE (1u << 19)
#define HASH_MASK  (TABLE_SIZE - 1u)
#define P2 2654435761u
#define P3 805459861u

#define CAP   2097152      // max points supported by sort path (N = 2,000,000)
#define NBINS (1u << 18)   // 64^3 Morton bins
#define SCAN_BLOCKS 256    // 256 blocks x 1024 threads covers NBINS

struct LevelCfg {
    float scale[NUM_LEVELS];
    unsigned int res[NUM_LEVELS];
};

// ---- scratch (static __device__ globals; no allocation) ----
__device__ float4       g_pts[CAP];        // sorted: (tx,ty,tz, bit-cast original idx)
__device__ unsigned int g_hist[NBINS];
__device__ unsigned int g_scan[NBINS];
__device__ unsigned int g_cursor[NBINS];
__device__ unsigned int g_bsum[SCAN_BLOCKS];
__device__ unsigned int g_bsumscan[SCAN_BLOCKS];

// ---- MLP weights in constant memory (uniform-const port, off the L1TEX pipe) ----
__constant__ float cW1[1024];
__constant__ float cW2[1024];
__constant__ float cW3[128];

// ---- helpers ----
__device__ __forceinline__ unsigned int expand_bits(unsigned int v) {
    v = (v * 0x00010001u) & 0xFF0000FFu;
    v = (v * 0x00000101u) & 0x0F00F00Fu;
    v = (v * 0x00000011u) & 0xC30C30C3u;
    v = (v * 0x00000005u) & 0x49249249u;
    return v;
}

__device__ __forceinline__ void norm_coords(const float* __restrict__ points,
                                            const float* __restrict__ aabb,
                                            int n, float& tx, float& ty, float& tz)
{
    float a0 = __ldg(aabb + 0), a1 = __ldg(aabb + 1), a2 = __ldg(aabb + 2);
    float b0 = __ldg(aabb + 3), b1 = __ldg(aabb + 4), b2 = __ldg(aabb + 5);
    tx = fminf(fmaxf((points[3 * n + 0] - a0) / (b0 - a0), 0.0f), 1.0f);
    ty = fminf(fmaxf((points[3 * n + 1] - a1) / (b1 - a1), 0.0f), 1.0f);
    tz = fminf(fmaxf((points[3 * n + 2] - a2) / (b2 - a2), 0.0f), 1.0f);
}

__device__ __forceinline__ unsigned int morton_bin(float tx, float ty, float tz) {
    unsigned int bx = min((unsigned int)(tx * 64.0f), 63u);
    unsigned int by = min((unsigned int)(ty * 64.0f), 63u);
    unsigned int bz = min((unsigned int)(tz * 64.0f), 63u);
    return expand_bits(bx) | (expand_bits(by) << 1) | (expand_bits(bz) << 2);
}

// ---- sort pipeline kernels ----
__global__ void zero_hist_kernel() {
    unsigned int i = blockIdx.x * blockDim.x + threadIdx.x;
    uint4 z = make_uint4(0u, 0u, 0u, 0u);
    if (i < NBINS / 4) reinterpret_cast<uint4*>(g_hist)[i] = z;
}

__global__ void hist_kernel(const float* __restrict__ points,
                            const float* __restrict__ aabb, int N) {
    int n = blockIdx.x * blockDim.x + threadIdx.x;
    if (n >= N) return;
    float tx, ty, tz;
    norm_coords(points, aabb, n, tx, ty, tz);
    atomicAdd(&g_hist[morton_bin(tx, ty, tz)], 1u);
}

// per-block (1024-bin) inclusive scan, warp-shuffle based
__global__ void scan1_kernel() {
    __shared__ unsigned int warp_sums[32];
    unsigned int i = blockIdx.x * 1024 + threadIdx.x;
    unsigned int lane = threadIdx.x & 31u;
    unsigned int warp = threadIdx.x >> 5;

    unsigned int v = g_hist[i];
    unsigned int x = v;
#pragma unroll
    for (int off = 1; off < 32; off <<= 1) {
        unsigned int t = __shfl_up_sync(0xFFFFFFFFu, x, off);
        if (lane >= (unsigned)off) x += t;
    }
    if (lane == 31u) warp_sums[warp] = x;
    __syncthreads();
    if (warp == 0u) {
        unsigned int s = warp_sums[lane];
#pragma unroll
        for (int off = 1; off < 32; off <<= 1) {
            unsigned int t = __shfl_up_sync(0xFFFFFFFFu, s, off);
            if (lane >= (unsigned)off) s += t;
        }
        warp_sums[lane] = s;
    }
    __syncthreads();
    unsigned int incl = x + (warp > 0u ? warp_sums[warp - 1u] : 0u);
    g_scan[i] = incl;
    if (threadIdx.x == 1023u) g_bsum[blockIdx.x] = incl;
}

__global__ void scan2_kernel() {  // exclusive scan of block sums (1 block, 256 thr)
    __shared__ unsigned int warp_sums[8];
    unsigned int t = threadIdx.x;
    unsigned int lane = t & 31u, warp = t >> 5;
    unsigned int v = g_bsum[t];
    unsigned int x = v;
#pragma unroll
    for (int off = 1; off < 32; off <<= 1) {
        unsigned int y = __shfl_up_sync(0xFFFFFFFFu, x, off);
        if (lane >= (unsigned)off) x += y;
    }
    if (lane == 31u) warp_sums[warp] = x;
    __syncthreads();
    if (warp == 0u && lane < 8u) {
        unsigned int s = warp_sums[lane];
#pragma unroll
        for (int off = 1; off < 8; off <<= 1) {
            unsigned int y = __shfl_up_sync(0xFFu, s, off);
            if (lane >= (unsigned)off) s += y;
        }
        warp_sums[lane] = s;
    }
    __syncthreads();
    unsigned int incl = x + (warp > 0u ? warp_sums[warp - 1u] : 0u);
    g_bsumscan[t] = incl - v;  // exclusive
}

__global__ void scan3_kernel() {  // global exclusive offsets -> cursors
    unsigned int i = blockIdx.x * 1024 + threadIdx.x;
    g_cursor[i] = g_scan[i] - g_hist[i] + g_bsumscan[blockIdx.x];
}

__global__ void scatter_kernel(const float* __restrict__ points,
                               const float* __restrict__ aabb, int N) {
    int n = blockIdx.x * blockDim.x + threadIdx.x;
    if (n >= N) return;
    float tx, ty, tz;
    norm_coords(points, aabb, n, tx, ty, tz);
    unsigned int p = atomicAdd(&g_cursor[morton_bin(tx, ty, tz)], 1u);
    g_pts[p] = make_float4(tx, ty, tz, __uint_as_float((unsigned int)n));
}

__global__ void stage_identity_kernel(const float* __restrict__ points,
                                      const float* __restrict__ aabb, int N) {
    int n = blockIdx.x * blockDim.x + threadIdx.x;
    if (n >= N) return;
    float tx, ty, tz;
    norm_coords(points, aabb, n, tx, ty, tz);
    g_pts[n] = make_float4(tx, ty, tz, __uint_as_float((unsigned int)n));
}

// Load a corner x-pair (iA, iB): adjacent+aligned -> one LDG.128.
__device__ __forceinline__ void load_pair(const float2* __restrict__ tab,
                                          unsigned int iA, unsigned int iB,
                                          float2& vA, float2& vB)
{
    if (((iA & 1u) == 0u) && (iB == iA + 1u)) {
        float4 t = __ldg(reinterpret_cast<const float4*>(tab + iA));
        vA.x = t.x; vA.y = t.y;
        vB.x = t.z; vB.y = t.w;
    } else {
        vA = __ldg(tab + iA);
        vB = __ldg(tab + iB);
    }
}

// NOTE: no min-blocks clause — forcing occupancy caused spills (R11 regression).
// This kernel hides latency via ILP (batched gathers), not warp count.
__global__ void __launch_bounds__(128)
hashmlp_kernel(const float* __restrict__ tables,
               float* __restrict__ out,
               int N, LevelCfg cfg)
{
    int n = blockIdx.x * blockDim.x + threadIdx.x;
    if (n >= N) return;

    float4 p = g_pts[n];
    float tx = p.x, ty = p.y, tz = p.z;
    unsigned int n_out = __float_as_uint(p.w);

    float h1[32];
#pragma unroll
    for (int i = 0; i < 32; i++) h1[i] = 0.0f;

#pragma unroll
    for (int l = 0; l < NUM_LEVELS; l++) {
        float sc = cfg.scale[l];
        unsigned int res = cfg.res[l];

        float fpx = tx * sc + 0.5f;
        float fpy = ty * sc + 0.5f;
        float fpz = tz * sc + 0.5f;
        float flx = floorf(fpx), fly = floorf(fpy), flz = floorf(fpz);
        float wx = fpx - flx, wy = fpy - fly, wz = fpz - flz;
        unsigned int bx = (unsigned int)flx;
        unsigned int by = (unsigned int)fly;
        unsigned int bz = (unsigned int)flz;
        unsigned int rm1 = res - 1u;
        unsigned int x0 = min(bx, rm1),      x1 = min(bx + 1u, rm1);
        unsigned int y0 = min(by, rm1),      y1 = min(by + 1u, rm1);
        unsigned int z0 = min(bz, rm1),      z1 = min(bz + 1u, rm1);

        unsigned int i0, i1, i2, i3, i4, i5, i6, i7;
        if (l <= 4) {
            unsigned int rr = res * res;
            unsigned int Y0 = y0 * res, Y1 = y1 * res;
            unsigned int Z0 = z0 * rr,  Z1 = z1 * rr;
            i0 = x0 + Y0 + Z0; i1 = x1 + Y0 + Z0;
            i2 = x0 + Y1 + Z0; i3 = x1 + Y1 + Z0;
            i4 = x0 + Y0 + Z1; i5 = x1 + Y0 + Z1;
            i6 = x0 + Y1 + Z1; i7 = x1 + Y1 + Z1;
        } else {
            unsigned int Y0 = y0 * P2, Y1 = y1 * P2;
            unsigned int Z0 = z0 * P3, Z1 = z1 * P3;
            i0 = (x0 ^ Y0 ^ Z0) & HASH_MASK; i1 = (x1 ^ Y0 ^ Z0) & HASH_MASK;
            i2 = (x0 ^ Y1 ^ Z0) & HASH_MASK; i3 = (x1 ^ Y1 ^ Z0) & HASH_MASK;
            i4 = (x0 ^ Y0 ^ Z1) & HASH_MASK; i5 = (x1 ^ Y0 ^ Z1) & HASH_MASK;
            i6 = (x0 ^ Y1 ^ Z1) & HASH_MASK; i7 = (x1 ^ Y1 ^ Z1) & HASH_MASK;
        }

        const float2* tab = reinterpret_cast<const float2*>(tables) + (size_t)l * TABLE_SIZE;
        float2 v0, v1, v2, v3, v4, v5, v6, v7;
        load_pair(tab, i0, i1, v0, v1);
        load_pair(tab, i2, i3, v2, v3);
        load_pair(tab, i4, i5, v4, v5);
        load_pair(tab, i6, i7, v6, v7);

        float ox = 1.0f - wx, oy = 1.0f - wy, oz = 1.0f - wz;
        float w0 = ox * oy * oz, w1c = wx * oy * oz;
        float w2c = ox * wy * oz, w3c = wx * wy * oz;
        float w4c = ox * oy * wz, w5c = wx * oy * wz;
        float w6c = ox * wy * wz, w7c = wx * wy * wz;

        float f0 = w0 * v0.x;
        float f1 = w0 * v0.y;
        f0 = fmaf(w1c, v1.x, f0); f1 = fmaf(w1c, v1.y, f1);
        f0 = fmaf(w2c, v2.x, f0); f1 = fmaf(w2c, v2.y, f1);
        f0 = fmaf(w3c, v3.x, f0); f1 = fmaf(w3c, v3.y, f1);
        f0 = fmaf(w4c, v4.x, f0); f1 = fmaf(w4c, v4.y, f1);
        f0 = fmaf(w5c, v5.x, f0); f1 = fmaf(w5c, v5.y, f1);
        f0 = fmaf(w6c, v6.x, f0); f1 = fmaf(w6c, v6.y, f1);
        f0 = fmaf(w7c, v7.x, f0); f1 = fmaf(w7c, v7.y, f1);

        // Fused layer-1 accumulation; cW1 offsets are compile-time constants.
#pragma unroll
        for (int i = 0; i < 32; i++) {
            h1[i] = fmaf(cW1[i * 32 + 2 * l], f0,
                    fmaf(cW1[i * 32 + 2 * l + 1], f1, h1[i]));
        }
    }

#pragma unroll
    for (int i = 0; i < 32; i++) h1[i] = fmaxf(h1[i], 0.0f);

    // Layers 2+3 fused streaming: h2_i computed then immediately consumed.
    // (Natural register reduction, no forced cap.)
    float o0 = 0.0f, o1 = 0.0f, o2 = 0.0f, o3 = 0.0f;
#pragma unroll
    for (int i = 0; i < 32; i++) {
        float acc = 0.0f;
#pragma unroll
        for (int j = 0; j < 32; j++) acc = fmaf(cW2[i * 32 + j], h1[j], acc);
        acc = fmaxf(acc, 0.0f);
        o0 = fmaf(cW3[0 * 32 + i], acc, o0);
        o1 = fmaf(cW3[1 * 32 + i], acc, o1);
        o2 = fmaf(cW3[2 * 32 + i], acc, o2);
        o3 = fmaf(cW3[3 * 32 + i], acc, o3);
    }

    float4 r;
    r.x = 1.0f / (1.0f + __expf(-o0));
    r.y = 1.0f / (1.0f + __expf(-o1));
    r.z = 1.0f / (1.0f + __expf(-o2));
    r.w = 1.0f / (1.0f + __expf(-o3)) * 0.99f + 0.01f;

    reinterpret_cast<float4*>(out)[n_out] = r;
}

extern "C" void kernel_launch(void* const* d_in, const int* in_sizes, int n_in,
                              void* d_out, int out_size)
{
    const float* points = (const float*)d_in[0];
    const float* tables = (const float*)d_in[1];
    const float* W1     = (const float*)d_in[2];
    const float* W2     = (const float*)d_in[3];
    const float* W3     = (const float*)d_in[4];
    const float* aabb   = (const float*)d_in[5];
    float* out = (float*)d_out;

    int N = in_sizes[0] / 3;

    LevelCfg cfg;
    double s = exp(log(4096.0 / 16.0) / (double)(NUM_LEVELS - 1));
    for (int l = 0; l < NUM_LEVELS; l++) {
        double sc = 16.0 * pow(s, (double)l) - 1.0;
        cfg.scale[l] = (float)sc;
        cfg.res[l]   = (unsigned int)ceil(sc) + 1u;
    }

    // Weights -> constant memory (D2D async copies; graph-capturable, no allocs)
    cudaMemcpyToSymbolAsync(cW1, W1, 1024 * sizeof(float), 0, cudaMemcpyDeviceToDevice);
    cudaMemcpyToSymbolAsync(cW2, W2, 1024 * sizeof(float), 0, cudaMemcpyDeviceToDevice);
    cudaMemcpyToSymbolAsync(cW3, W3, 128 * sizeof(float), 0, cudaMemcpyDeviceToDevice);

    int block = 256;
    int pgrid = (N + block - 1) / block;

    if (N <= CAP) {
        zero_hist_kernel<<<(NBINS / 4 + 255) / 256, 256>>>();
        hist_kernel<<<pgrid, block>>>(points, aabb, N);
        scan1_kernel<<<SCAN_BLOCKS, 1024>>>();
        scan2_kernel<<<1, SCAN_BLOCKS>>>();
        scan3_kernel<<<SCAN_BLOCKS, 1024>>>();
        scatter_kernel<<<pgrid, block>>>(points, aabb, N);
    } else {
        stage_identity_kernel<<<pgrid, block>>>(points, aabb, N);
    }

    int mblock = 128;
    int mgrid = (N + mblock - 1) / mblock;
    hashmlp_kernel<<<mgrid, mblock>>>(tables, out, N, cfg);
}